// round 4
// baseline (speedup 1.0000x reference)
#include <cuda_runtime.h>
#include <cuda_bf16.h>
#include <cstdint>

// ---------------- problem constants ----------------
constexpr int   NROWS = 200000;
constexpr int   ODIM  = 8;
constexpr long long X1_ELEMS = (long long)ODIM * NROWS * 64;      // 102,400,000
constexpr long long DAGS_OFF = X1_ELEMS;
constexpr long long REG_OFF  = DAGS_OFF + (long long)ODIM * 64 * 64;

constexpr int TILE_M  = 256;
constexpr int THREADS = 256;
constexpr int NTILES  = (NROWS + TILE_M - 1) / TILE_M;            // 782

// ---------------- smem layout ----------------
// A region (64KB): bf16 hi [0,32K) + lo [32K,64K); reused as fp32 epilogue
// buffer (256 rows x 64 cols x 4B = 64KB) after A fragments are in registers.
constexpr int OFF_AHI = 0;
constexpr int OFF_ALO = 32768;
constexpr int OFF_EPI = 0;
constexpr int OFF_BHI = 65536;              // 64 rows (c) x 128 B bf16 [c][p]
constexpr int OFF_BLO = OFF_BHI + 8192;
constexpr int SMEM_BYTES = OFF_BLO + 8192;  // 81920

#define SWZ128(x) ((x) ^ (((x) >> 3) & 0x70))

// ---------------- global scratch (bf16 split of dags*W, [o][c][p]) ----------------
__device__ __nv_bfloat16 g_WMhi[ODIM * 64 * 64];
__device__ __nv_bfloat16 g_WMlo[ODIM * 64 * 64];

// ---------------- PTX helpers ----------------
__device__ __forceinline__ uint32_t smem_u32(const void* p) {
    uint32_t a;
    asm("{ .reg .u64 t; cvta.to.shared.u64 t, %1; cvt.u32.u64 %0, t; }" : "=r"(a) : "l"(p));
    return a;
}
__device__ __forceinline__ void ldm_x4(uint32_t addr, uint32_t* r) {
    asm volatile("ldmatrix.sync.aligned.m8n8.x4.shared.b16 {%0,%1,%2,%3}, [%4];"
                 : "=r"(r[0]), "=r"(r[1]), "=r"(r[2]), "=r"(r[3]) : "r"(addr));
}
__device__ __forceinline__ void ldm_x2(uint32_t addr, uint32_t* r) {
    asm volatile("ldmatrix.sync.aligned.m8n8.x2.shared.b16 {%0,%1}, [%2];"
                 : "=r"(r[0]), "=r"(r[1]) : "r"(addr));
}
__device__ __forceinline__ void mma_bf16(float* d, const uint32_t* a, const uint32_t* b) {
    asm volatile("mma.sync.aligned.m16n8k16.row.col.f32.bf16.bf16.f32 "
                 "{%0,%1,%2,%3}, {%4,%5,%6,%7}, {%8,%9}, {%0,%1,%2,%3};"
                 : "+f"(d[0]), "+f"(d[1]), "+f"(d[2]), "+f"(d[3])
                 : "r"(a[0]), "r"(a[1]), "r"(a[2]), "r"(a[3]), "r"(b[0]), "r"(b[1]));
}

// ---------------- prep: WM split + dags copy + reg ----------------
__global__ void prep_kernel(const float* __restrict__ dags,
                            const float* __restrict__ W,
                            float* __restrict__ out)
{
    const int o   = blockIdx.x;
    const int tid = threadIdx.x;
    const float* dg = dags + (size_t)o * 4096;
    const float* ww = W    + (size_t)o * 4096;
    float* od = out + DAGS_OFF + (size_t)o * 4096;

    float s = 0.f;
    #pragma unroll
    for (int i = 0; i < 16; i++) {
        int j = tid + 256 * i;           // j = p*64 + c
        float d = dg[j];
        float w = ww[j];
        od[j] = d;
        s += w * w;
        float wm = d * w;
        __nv_bfloat16 hi = __float2bfloat16(wm);
        float lo = wm - __bfloat162float(hi);
        int p = j >> 6, c = j & 63;
        int t = (o << 12) | (c << 6) | p;   // [o][c][p]
        g_WMhi[t] = hi;
        g_WMlo[t] = __float2bfloat16(lo);
    }
    #pragma unroll
    for (int off = 16; off > 0; off >>= 1) s += __shfl_xor_sync(0xFFFFFFFFu, s, off);
    __shared__ float ws[8];
    if ((tid & 31) == 0) ws[tid >> 5] = s;
    __syncthreads();
    if (tid < 32) {
        float t = (tid < 8) ? ws[tid] : 0.f;
        #pragma unroll
        for (int off = 4; off > 0; off >>= 1) t += __shfl_xor_sync(0xFFFFFFFFu, t, off);
        if (tid == 0) out[REG_OFF + o] = 0.001f * t;
    }
}

// ---------------- HMMA GEMM: x1[o,n,c] = sum_p X[n,p] * WM[o,p,c] ----------------
__global__ void __launch_bounds__(THREADS, 2)
gemm_kernel(const float* __restrict__ X, float* __restrict__ out)
{
    extern __shared__ char smem[];
    const uint32_t sb  = smem_u32(smem);
    const int tid  = threadIdx.x;
    const int wid  = tid >> 5;
    const int lane = tid & 31;
    const int n0   = blockIdx.x * TILE_M;

    // ---- X tile (256 rows) -> bf16 hi/lo, SW128-swizzled smem ----
    {
        const float2* X2 = reinterpret_cast<const float2*>(X);
        #pragma unroll
        for (int i = tid; i < 8192; i += THREADS) {
            int row = i >> 5, pp = i & 31;
            int n = n0 + row;
            float2 v = (n < NROWS) ? X2[(size_t)n * 32 + pp] : make_float2(0.f, 0.f);
            __nv_bfloat16 h0 = __float2bfloat16(v.x);
            __nv_bfloat16 h1 = __float2bfloat16(v.y);
            __nv_bfloat16 g0 = __float2bfloat16(v.x - __bfloat162float(h0));
            __nv_bfloat16 g1 = __float2bfloat16(v.y - __bfloat162float(h1));
            uint32_t hp = (uint32_t)__bfloat16_as_ushort(h0) |
                          ((uint32_t)__bfloat16_as_ushort(h1) << 16);
            uint32_t lp = (uint32_t)__bfloat16_as_ushort(g0) |
                          ((uint32_t)__bfloat16_as_ushort(g1) << 16);
            uint32_t off = SWZ128((uint32_t)(row * 128 + pp * 4));
            *reinterpret_cast<uint32_t*>(smem + OFF_AHI + off) = hp;
            *reinterpret_cast<uint32_t*>(smem + OFF_ALO + off) = lp;
        }
    }
    __syncthreads();

    // ---- Preload A fragments (warp rows wid*32..+31), reused across all o ----
    uint32_t afrag[2][4][2][4];
    #pragma unroll
    for (int mt = 0; mt < 2; mt++) {
        #pragma unroll
        for (int ks = 0; ks < 4; ks++) {
            int r  = wid * 32 + mt * 16 + (lane & 15);
            int kb = ks * 32 + (lane >> 4) * 16;
            uint32_t off = SWZ128((uint32_t)(r * 128 + kb));
            ldm_x4(sb + OFF_AHI + off, afrag[mt][ks][0]);
            ldm_x4(sb + OFF_ALO + off, afrag[mt][ks][1]);
        }
    }

    // ---- stage B(0) ----
    {
        const uint4* bh = reinterpret_cast<const uint4*>(g_WMhi);
        const uint4* bl = reinterpret_cast<const uint4*>(g_WMlo);
        #pragma unroll
        for (int i = tid; i < 512; i += THREADS) {   // 2 iters
            int row = i >> 3, q = i & 7;
            uint32_t off = SWZ128((uint32_t)(row * 128 + q * 16));
            *reinterpret_cast<uint4*>(smem + OFF_BHI + off) = bh[i];
            *reinterpret_cast<uint4*>(smem + OFF_BLO + off) = bl[i];
        }
    }
    __syncthreads();   // afrag ldm done (A region free) + B(0) visible

    const uint32_t b_off_base = (uint32_t)((lane & 7) * 128 + ((lane >> 3) & 1) * 16);
    // epilogue smem addressing constants
    const int epi_row_base = wid * 32;            // + mt*16 + rh*8 + (lane>>2)
    const int swz_key      = (lane >> 2);         // row & 7

    for (int o = 0; o < 8; o++) {
        // prefetch B(o+1) into regs (2 hi + 2 lo uint4 per thread)
        uint4 pre[4];
        if (o < 7) {
            const uint4* bh = reinterpret_cast<const uint4*>(g_WMhi + (o + 1) * 4096);
            const uint4* bl = reinterpret_cast<const uint4*>(g_WMlo + (o + 1) * 4096);
            pre[0] = bh[tid];
            pre[1] = bh[tid + 256];
            pre[2] = bl[tid];
            pre[3] = bl[tid + 256];
        }

        // ---- MMA loop; fragments go straight into the EPI smem buffer ----
        #pragma unroll
        for (int nt = 0; nt < 8; nt++) {
            float acc[2][4];
            #pragma unroll
            for (int mt = 0; mt < 2; mt++)
                #pragma unroll
                for (int j = 0; j < 4; j++) acc[mt][j] = 0.f;

            #pragma unroll
            for (int ks = 0; ks < 4; ks++) {
                uint32_t bhi[2], blo[2];
                uint32_t boff = SWZ128(b_off_base + (uint32_t)(nt * 8 * 128 + ks * 32));
                ldm_x2(sb + OFF_BHI + boff, bhi);
                ldm_x2(sb + OFF_BLO + boff, blo);
                #pragma unroll
                for (int mt = 0; mt < 2; mt++) {
                    mma_bf16(acc[mt], afrag[mt][ks][0], bhi);   // Ahi*Bhi
                    mma_bf16(acc[mt], afrag[mt][ks][1], bhi);   // Alo*Bhi
                    mma_bf16(acc[mt], afrag[mt][ks][0], blo);   // Ahi*Blo
                }
            }

            // STS fragments: row = epi_row_base + mt*16 + rh*8 + (lane>>2)
            // phys f2 slot = (nt*4 + (lane&3) + 4*(row&7)) & 31  -> conflict-free
            uint32_t slot = (uint32_t)((nt * 4 + (lane & 3) + 4 * swz_key) & 31);
            #pragma unroll
            for (int mt = 0; mt < 2; mt++) {
                int r0 = epi_row_base + mt * 16 + (lane >> 2);
                *reinterpret_cast<float2*>(smem + OFF_EPI + r0 * 256 + slot * 8) =
                    make_float2(acc[mt][0], acc[mt][1]);
                *reinterpret_cast<float2*>(smem + OFF_EPI + (r0 + 8) * 256 + slot * 8) =
                    make_float2(acc[mt][2], acc[mt][3]);
            }
        }
        __syncthreads();   // EPI complete; all MMAs done -> B region free

        // stage B(o+1) from regs (not read until after next sync)
        if (o < 7) {
            int row0 = tid >> 3, q0 = tid & 7;            // i = tid
            int row1 = (tid + 256) >> 3, q1 = tid & 7;    // i = tid+256
            uint32_t o0 = SWZ128((uint32_t)(row0 * 128 + q0 * 16));
            uint32_t o1 = SWZ128((uint32_t)(row1 * 128 + q1 * 16));
            *reinterpret_cast<uint4*>(smem + OFF_BHI + o0) = pre[0];
            *reinterpret_cast<uint4*>(smem + OFF_BHI + o1) = pre[1];
            *reinterpret_cast<uint4*>(smem + OFF_BLO + o0) = pre[2];
            *reinterpret_cast<uint4*>(smem + OFF_BLO + o1) = pre[3];
        }

        // ---- coalesced readback: LDS.128 + STG.128 ----
        float* x1 = out + (size_t)o * NROWS * 64;
        #pragma unroll
        for (int i = 0; i < 16; i++) {
            int idx = tid + THREADS * i;      // f4 index
            int row = idx >> 4, G = idx & 15;
            uint32_t phys = (uint32_t)((2 * G + 4 * (row & 7)) & 31);
            float4 v = *reinterpret_cast<const float4*>(smem + OFF_EPI + row * 256 + phys * 8);
            int n = n0 + row;
            if (n < NROWS)
                *reinterpret_cast<float4*>(x1 + (size_t)n * 64 + G * 4) = v;
        }
        __syncthreads();   // EPI reads done before next o overwrites; B(o+1) visible
    }
}

// ---------------- launch ----------------
extern "C" void kernel_launch(void* const* d_in, const int* in_sizes, int n_in,
                              void* d_out, int out_size)
{
    const float* X    = (const float*)d_in[0];
    const float* dags = (const float*)d_in[1];
    const float* W    = (const float*)d_in[2];
    float* out = (float*)d_out;

    static bool attr_set = false;
    if (!attr_set) {
        cudaFuncSetAttribute(gemm_kernel,
                             cudaFuncAttributeMaxDynamicSharedMemorySize, SMEM_BYTES);
        attr_set = true;
    }

    prep_kernel<<<ODIM, 256>>>(dags, W, out);
    gemm_kernel<<<NTILES, THREADS, SMEM_BYTES>>>(X, out);
}

// round 5
// speedup vs baseline: 1.2866x; 1.2866x over previous
#include <cuda_runtime.h>
#include <cuda_bf16.h>
#include <cstdint>

// ---------------- problem constants ----------------
constexpr int   NROWS = 200000;
constexpr int   ODIM  = 8;
constexpr long long X1_ELEMS = (long long)ODIM * NROWS * 64;      // 102,400,000
constexpr long long DAGS_OFF = X1_ELEMS;
constexpr long long REG_OFF  = DAGS_OFF + (long long)ODIM * 64 * 64;

constexpr int TILE_M  = 512;
constexpr int THREADS = 512;
constexpr int NTILES  = (NROWS + TILE_M - 1) / TILE_M;            // 391

// ---------------- smem layout (128KB, two overlaid phases) ----------------
// Phase 1 (A staging):   AHI [0,64K), ALO [64K,128K)  (512 rows x 128B bf16)
// Phase 2 (B resident):  per o: base = o*16KB, hi at +0, lo at +8K
constexpr int OFF_AHI = 0;
constexpr int OFF_ALO = 65536;
constexpr int SMEM_BYTES = 131072;

#define SWZ128(x) ((x) ^ (((x) >> 3) & 0x70))

// ---------------- global scratch (bf16 split of dags*W, [o][c][p]) ----------------
__device__ __nv_bfloat16 g_WMhi[ODIM * 64 * 64];
__device__ __nv_bfloat16 g_WMlo[ODIM * 64 * 64];

// ---------------- PTX helpers ----------------
__device__ __forceinline__ uint32_t smem_u32(const void* p) {
    uint32_t a;
    asm("{ .reg .u64 t; cvta.to.shared.u64 t, %1; cvt.u32.u64 %0, t; }" : "=r"(a) : "l"(p));
    return a;
}
__device__ __forceinline__ void ldm_x4(uint32_t addr, uint32_t* r) {
    asm volatile("ldmatrix.sync.aligned.m8n8.x4.shared.b16 {%0,%1,%2,%3}, [%4];"
                 : "=r"(r[0]), "=r"(r[1]), "=r"(r[2]), "=r"(r[3]) : "r"(addr));
}
__device__ __forceinline__ void mma_bf16(float* d, const uint32_t* a, const uint32_t* b) {
    asm volatile("mma.sync.aligned.m16n8k16.row.col.f32.bf16.bf16.f32 "
                 "{%0,%1,%2,%3}, {%4,%5,%6,%7}, {%8,%9}, {%0,%1,%2,%3};"
                 : "+f"(d[0]), "+f"(d[1]), "+f"(d[2]), "+f"(d[3])
                 : "r"(a[0]), "r"(a[1]), "r"(a[2]), "r"(a[3]), "r"(b[0]), "r"(b[1]));
}

// ---------------- prep: WM split + dags copy + reg ----------------
__global__ void prep_kernel(const float* __restrict__ dags,
                            const float* __restrict__ W,
                            float* __restrict__ out)
{
    const int o   = blockIdx.x;
    const int tid = threadIdx.x;
    const float* dg = dags + (size_t)o * 4096;
    const float* ww = W    + (size_t)o * 4096;
    float* od = out + DAGS_OFF + (size_t)o * 4096;

    float s = 0.f;
    #pragma unroll
    for (int i = 0; i < 16; i++) {
        int j = tid + 256 * i;           // j = p*64 + c
        float d = dg[j];
        float w = ww[j];
        od[j] = d;
        s += w * w;
        float wm = d * w;
        __nv_bfloat16 hi = __float2bfloat16(wm);
        float lo = wm - __bfloat162float(hi);
        int p = j >> 6, c = j & 63;
        int t = (o << 12) | (c << 6) | p;   // [o][c][p]
        g_WMhi[t] = hi;
        g_WMlo[t] = __float2bfloat16(lo);
    }
    #pragma unroll
    for (int off = 16; off > 0; off >>= 1) s += __shfl_xor_sync(0xFFFFFFFFu, s, off);
    __shared__ float ws[8];
    if ((tid & 31) == 0) ws[tid >> 5] = s;
    __syncthreads();
    if (tid < 32) {
        float t = (tid < 8) ? ws[tid] : 0.f;
        #pragma unroll
        for (int off = 4; off > 0; off >>= 1) t += __shfl_xor_sync(0xFFFFFFFFu, t, off);
        if (tid == 0) out[REG_OFF + o] = 0.001f * t;
    }
}

// ---------------- HMMA GEMM: x1[o,n,c] = sum_p X[n,p] * WM[o,p,c] ----------------
__global__ void __launch_bounds__(THREADS, 1)
gemm_kernel(const float* __restrict__ X, float* __restrict__ out)
{
    extern __shared__ char smem[];
    const uint32_t sb  = smem_u32(smem);
    const int tid  = threadIdx.x;
    const int wid  = tid >> 5;
    const int lane = tid & 31;
    const int n0   = blockIdx.x * TILE_M;

    // ---- Phase 1: X tile (512 rows) -> bf16 hi/lo, SW128-swizzled smem ----
    {
        const float2* X2 = reinterpret_cast<const float2*>(X);
        #pragma unroll
        for (int i = tid; i < 16384; i += THREADS) {
            int row = i >> 5, pp = i & 31;
            int n = n0 + row;
            float2 v = (n < NROWS) ? X2[(size_t)n * 32 + pp] : make_float2(0.f, 0.f);
            __nv_bfloat16 h0 = __float2bfloat16(v.x);
            __nv_bfloat16 h1 = __float2bfloat16(v.y);
            __nv_bfloat16 g0 = __float2bfloat16(v.x - __bfloat162float(h0));
            __nv_bfloat16 g1 = __float2bfloat16(v.y - __bfloat162float(h1));
            uint32_t hp = (uint32_t)__bfloat16_as_ushort(h0) |
                          ((uint32_t)__bfloat16_as_ushort(h1) << 16);
            uint32_t lp = (uint32_t)__bfloat16_as_ushort(g0) |
                          ((uint32_t)__bfloat16_as_ushort(g1) << 16);
            uint32_t off = SWZ128((uint32_t)(row * 128 + pp * 4));
            *reinterpret_cast<uint32_t*>(smem + OFF_AHI + off) = hp;
            *reinterpret_cast<uint32_t*>(smem + OFF_ALO + off) = lp;
        }
    }
    __syncthreads();

    // ---- Preload A fragments (warp rows wid*32..+31), reused across all o ----
    uint32_t afrag[2][4][2][4];
    #pragma unroll
    for (int mt = 0; mt < 2; mt++) {
        #pragma unroll
        for (int ks = 0; ks < 4; ks++) {
            int r  = wid * 32 + mt * 16 + (lane & 15);
            int kb = ks * 32 + (lane >> 4) * 16;
            uint32_t off = SWZ128((uint32_t)(r * 128 + kb));
            ldm_x4(sb + OFF_AHI + off, afrag[mt][ks][0]);
            ldm_x4(sb + OFF_ALO + off, afrag[mt][ks][1]);
        }
    }
    __syncthreads();   // A region fully consumed into registers

    // ---- Phase 2: stage ALL B tiles (8 o x (hi 8K + lo 8K) = 128KB) ----
    {
        // 4096 uint4 for hi, 4096 for lo; each thread: 8 + 8
        const uint4* bh = reinterpret_cast<const uint4*>(g_WMhi);
        const uint4* bl = reinterpret_cast<const uint4*>(g_WMlo);
        #pragma unroll
        for (int i = tid; i < 4096; i += THREADS) {
            int o   = i >> 9;            // 512 uint4 per o
            int j   = i & 511;
            int row = j >> 3, q = j & 7; // row = c, q = 16B chunk along p
            uint32_t off = SWZ128((uint32_t)(row * 128 + q * 16));
            *reinterpret_cast<uint4*>(smem + o * 16384 + off)        = bh[i];
            *reinterpret_cast<uint4*>(smem + o * 16384 + 8192 + off) = bl[i];
        }
    }
    __syncthreads();   // last barrier — mainloop is fully barrier-free

    // B ldmatrix lane addressing: matrix m = lane>>3
    //   col_local = (lane&7) + (m>>1)*8 ; kbyte = (m&1)*16
    const int b_m    = lane >> 3;
    const int b_col  = (lane & 7) + ((b_m >> 1) << 3);
    const int b_kb   = (b_m & 1) << 4;

    for (int o = 0; o < 8; o++) {
        const uint32_t bhi_base = sb + o * 16384;
        const uint32_t blo_base = bhi_base + 8192;
        float* x1 = out + (size_t)o * NROWS * 64;

        #pragma unroll
        for (int nt2 = 0; nt2 < 4; nt2++) {       // 16 output cols per iter
            float acc[2][2][4];                    // [n-half][mt][4]
            #pragma unroll
            for (int h = 0; h < 2; h++)
                #pragma unroll
                for (int mt = 0; mt < 2; mt++)
                    #pragma unroll
                    for (int j = 0; j < 4; j++) acc[h][mt][j] = 0.f;

            #pragma unroll
            for (int ks = 0; ks < 4; ks++) {
                uint32_t bhi[4], blo[4];
                uint32_t boff = SWZ128((uint32_t)((nt2 * 16 + b_col) * 128 + ks * 32 + b_kb));
                ldm_x4(bhi_base + boff, bhi);
                ldm_x4(blo_base + boff, blo);
                #pragma unroll
                for (int h = 0; h < 2; h++) {
                    #pragma unroll
                    for (int mt = 0; mt < 2; mt++) {
                        mma_bf16(acc[h][mt], afrag[mt][ks][0], bhi + 2 * h);  // Ahi*Bhi
                        mma_bf16(acc[h][mt], afrag[mt][ks][1], bhi + 2 * h);  // Alo*Bhi
                        mma_bf16(acc[h][mt], afrag[mt][ks][0], blo + 2 * h);  // Ahi*Blo
                    }
                }
            }

            // ---- direct stores: float2, 32B-sector aligned ----
            #pragma unroll
            for (int h = 0; h < 2; h++) {
                int col = nt2 * 16 + h * 8 + (lane & 3) * 2;
                #pragma unroll
                for (int mt = 0; mt < 2; mt++) {
                    int row = n0 + wid * 32 + mt * 16 + (lane >> 2);
                    if (row < NROWS)
                        *reinterpret_cast<float2*>(x1 + (size_t)row * 64 + col) =
                            make_float2(acc[h][mt][0], acc[h][mt][1]);
                    if (row + 8 < NROWS)
                        *reinterpret_cast<float2*>(x1 + (size_t)(row + 8) * 64 + col) =
                            make_float2(acc[h][mt][2], acc[h][mt][3]);
                }
            }
        }
    }
}

// ---------------- launch ----------------
extern "C" void kernel_launch(void* const* d_in, const int* in_sizes, int n_in,
                              void* d_out, int out_size)
{
    const float* X    = (const float*)d_in[0];
    const float* dags = (const float*)d_in[1];
    const float* W    = (const float*)d_in[2];
    float* out = (float*)d_out;

    static bool attr_set = false;
    if (!attr_set) {
        cudaFuncSetAttribute(gemm_kernel,
                             cudaFuncAttributeMaxDynamicSharedMemorySize, SMEM_BYTES);
        attr_set = true;
    }

    prep_kernel<<<ODIM, 256>>>(dags, W, out);
    gemm_kernel<<<NTILES, THREADS, SMEM_BYTES>>>(X, out);
}